// round 7
// baseline (speedup 1.0000x reference)
#include <cuda_runtime.h>
#include <cuda_bf16.h>

#define HID 4096
#define MH 16384             // 4 * HIDDEN
#define TOK 4
#define NT 256
#define NWARP (NT / 32)      // 8
#define NK (MH / 4 / NT)     // 16 float4-iterations per token

__device__ __forceinline__ float bflo(unsigned u) {   // low bf16 -> f32
    return __uint_as_float(u << 16);
}
__device__ __forceinline__ float bfhi(unsigned u) {   // high bf16 -> f32
    return __uint_as_float(u & 0xFFFF0000u);
}
// round fp32 pair -> packed bf16x2 (RN, matches astype(bfloat16))
__device__ __forceinline__ unsigned pack_bf2(float a, float b) {
    __nv_bfloat162 p = __floats2bfloat162_rn(a, b);
    return *reinterpret_cast<unsigned*>(&p);
}

__global__ __launch_bounds__(NT, 4) void hchead_kernel(
    const float* __restrict__ x,
    const float* __restrict__ fn,
    const float* __restrict__ scale,
    const float* __restrict__ base,
    float* __restrict__ out)
{
    __shared__ float red[NWARP * 20];
    __shared__ float wsh[TOK * 4];

    const int tid  = threadIdx.x;
    const int warp = tid >> 5, lane = tid & 31;
    const size_t tok0 = (size_t)blockIdx.x * TOK;

    const float4* x4  = reinterpret_cast<const float4*>(x);
    const float4* fn4 = reinterpret_cast<const float4*>(fn);

    // acc: t*5+0 = sum(x^2), t*5+1+m = dot with fn[m]
    float acc[20];
#pragma unroll
    for (int i = 0; i < 20; i++) acc[i] = 0.f;

    // ------- Phase 1: stream x (DRAM) + fn (L2), accumulate sums -------
#pragma unroll
    for (int k = 0; k < NK; k++) {          // 16 iterations
        const int f = tid + k * NT;         // float4 index (j = 4f)
        const float4 g0 = fn4[0 * (MH / 4) + f];
        const float4 g1 = fn4[1 * (MH / 4) + f];
        const float4 g2 = fn4[2 * (MH / 4) + f];
        const float4 g3 = fn4[3 * (MH / 4) + f];
        float4 v0 = x4[(tok0 + 0) * (MH / 4) + f];
        float4 v1 = x4[(tok0 + 1) * (MH / 4) + f];
        float4 v2 = x4[(tok0 + 2) * (MH / 4) + f];
        float4 v3 = x4[(tok0 + 3) * (MH / 4) + f];
#pragma unroll
        for (int t = 0; t < TOK; t++) {
            const float4 v = (t == 0) ? v0 : (t == 1) ? v1 : (t == 2) ? v2 : v3;
            const unsigned p0 = pack_bf2(v.x, v.y);
            const unsigned p1 = pack_bf2(v.z, v.w);
            const float x0 = bflo(p0), x1 = bfhi(p0);
            const float x2 = bflo(p1), x3 = bfhi(p1);
            acc[t * 5 + 0] += x0 * x0 + x1 * x1 + x2 * x2 + x3 * x3;
            acc[t * 5 + 1] += x0 * g0.x + x1 * g0.y + x2 * g0.z + x3 * g0.w;
            acc[t * 5 + 2] += x0 * g1.x + x1 * g1.y + x2 * g1.z + x3 * g1.w;
            acc[t * 5 + 3] += x0 * g2.x + x1 * g2.y + x2 * g2.z + x3 * g2.w;
            acc[t * 5 + 4] += x0 * g3.x + x1 * g3.y + x2 * g3.z + x3 * g3.w;
        }
    }

    // ------- Block reduction of 20 partials -------
#pragma unroll
    for (int i = 0; i < 20; i++) {
#pragma unroll
        for (int o = 16; o > 0; o >>= 1)
            acc[i] += __shfl_xor_sync(0xffffffffu, acc[i], o);
    }
    if (lane == 0) {
#pragma unroll
        for (int i = 0; i < 20; i++) red[warp * 20 + i] = acc[i];
    }
    __syncthreads();

    if (tid < TOK) {
        const int t = tid;
        float ss = 0.f, d0 = 0.f, d1 = 0.f, d2 = 0.f, d3 = 0.f;
#pragma unroll
        for (int w = 0; w < NWARP; w++) {
            ss += red[w * 20 + t * 5 + 0];
            d0 += red[w * 20 + t * 5 + 1];
            d1 += red[w * 20 + t * 5 + 2];
            d2 += red[w * 20 + t * 5 + 3];
            d3 += red[w * 20 + t * 5 + 4];
        }
        const float inv = 1.0f / sqrtf(ss * (1.0f / MH) + 1e-6f);
        const float s = scale[0];
        const float a0 = s * (d0 * inv) + base[0];
        const float a1 = s * (d1 * inv) + base[1];
        const float a2 = s * (d2 * inv) + base[2];
        const float a3 = s * (d3 * inv) + base[3];
        const float idn = 1.0f / (fabsf(a0) + fabsf(a1) + fabsf(a2) + fabsf(a3) + 1e-6f);
        wsh[t * 4 + 0] = a0 * idn;
        wsh[t * 4 + 1] = a1 * idn;
        wsh[t * 4 + 2] = a2 * idn;
        wsh[t * 4 + 3] = a3 * idn;
    }
    __syncthreads();

    // ------- Phase 2: re-read x from L2, re-round, combine, store -------
    // 256 threads, 4096 h/token -> 16 h/thread = 2 groups of 8.
#pragma unroll
    for (int t = 0; t < TOK; t++) {
        const float w0 = wsh[t * 4 + 0], w1 = wsh[t * 4 + 1];
        const float w2 = wsh[t * 4 + 2], w3 = wsh[t * 4 + 3];
        const float4* xp = x4 + (tok0 + t) * (MH / 4);
        float* op_base = out + (tok0 + t) * HID;
#pragma unroll
        for (int g = 0; g < 2; g++) {
            const int h4 = (tid + g * NT) * 2;     // float4 index into hidden
            float4 a0 = xp[0 * (HID / 4) + h4 + 0];
            float4 a1 = xp[0 * (HID / 4) + h4 + 1];
            float4 b0 = xp[1 * (HID / 4) + h4 + 0];
            float4 b1 = xp[1 * (HID / 4) + h4 + 1];
            float4 c0 = xp[2 * (HID / 4) + h4 + 0];
            float4 c1 = xp[2 * (HID / 4) + h4 + 1];
            float4 d0 = xp[3 * (HID / 4) + h4 + 0];
            float4 d1 = xp[3 * (HID / 4) + h4 + 1];

            float r[8];
            {
                unsigned q0 = pack_bf2(a0.x, a0.y), q1 = pack_bf2(a0.z, a0.w);
                unsigned q2 = pack_bf2(a1.x, a1.y), q3 = pack_bf2(a1.z, a1.w);
                r[0] = w0 * bflo(q0); r[1] = w0 * bfhi(q0);
                r[2] = w0 * bflo(q1); r[3] = w0 * bfhi(q1);
                r[4] = w0 * bflo(q2); r[5] = w0 * bfhi(q2);
                r[6] = w0 * bflo(q3); r[7] = w0 * bfhi(q3);
            }
            {
                unsigned q0 = pack_bf2(b0.x, b0.y), q1 = pack_bf2(b0.z, b0.w);
                unsigned q2 = pack_bf2(b1.x, b1.y), q3 = pack_bf2(b1.z, b1.w);
                r[0] += w1 * bflo(q0); r[1] += w1 * bfhi(q0);
                r[2] += w1 * bflo(q1); r[3] += w1 * bfhi(q1);
                r[4] += w1 * bflo(q2); r[5] += w1 * bfhi(q2);
                r[6] += w1 * bflo(q3); r[7] += w1 * bfhi(q3);
            }
            {
                unsigned q0 = pack_bf2(c0.x, c0.y), q1 = pack_bf2(c0.z, c0.w);
                unsigned q2 = pack_bf2(c1.x, c1.y), q3 = pack_bf2(c1.z, c1.w);
                r[0] += w2 * bflo(q0); r[1] += w2 * bfhi(q0);
                r[2] += w2 * bflo(q1); r[3] += w2 * bfhi(q1);
                r[4] += w2 * bflo(q2); r[5] += w2 * bfhi(q2);
                r[6] += w2 * bflo(q3); r[7] += w2 * bfhi(q3);
            }
            {
                unsigned q0 = pack_bf2(d0.x, d0.y), q1 = pack_bf2(d0.z, d0.w);
                unsigned q2 = pack_bf2(d1.x, d1.y), q3 = pack_bf2(d1.z, d1.w);
                r[0] += w3 * bflo(q0); r[1] += w3 * bfhi(q0);
                r[2] += w3 * bflo(q1); r[3] += w3 * bfhi(q1);
                r[4] += w3 * bflo(q2); r[5] += w3 * bfhi(q2);
                r[6] += w3 * bflo(q3); r[7] += w3 * bfhi(q3);
            }

            float4* op = reinterpret_cast<float4*>(op_base) + h4;
            op[0] = make_float4(r[0], r[1], r[2], r[3]);
            op[1] = make_float4(r[4], r[5], r[6], r[7]);
        }
    }
}

extern "C" void kernel_launch(void* const* d_in, const int* in_sizes, int n_in,
                              void* d_out, int out_size) {
    const float* x     = (const float*)d_in[0];   // [T, 4*4096] fp32
    const float* fn    = (const float*)d_in[1];   // [4, 16384]  fp32
    const float* scale = (const float*)d_in[2];   // [1]
    const float* base  = (const float*)d_in[3];   // [4]
    float* out = (float*)d_out;                   // [T, 4096] fp32

    const int T = in_sizes[0] / MH;               // 8192
    hchead_kernel<<<T / TOK, NT>>>(x, fn, scale, base, out);
}

// round 8
// speedup vs baseline: 1.1738x; 1.1738x over previous
#include <cuda_runtime.h>
#include <cuda_bf16.h>

#define HID 4096
#define MH 16384             // 4 * HIDDEN
#define TOK 4
#define STOK 2               // tokens stashed in smem
#define NT 512
#define NWARP (NT / 32)      // 16
#define NK (MH / 4 / NT)     // 8 float4-iterations per token
// smem: 2 tokens bf16 (64 KB) + reduction scratch + weights
#define SMEM_BYTES (STOK * MH * 2 + (NWARP * 20 + TOK * 4) * 4)

__device__ __forceinline__ float bflo(unsigned u) {   // low bf16 -> f32
    return __uint_as_float(u << 16);
}
__device__ __forceinline__ float bfhi(unsigned u) {   // high bf16 -> f32
    return __uint_as_float(u & 0xFFFF0000u);
}
// round fp32 pair -> packed bf16x2 (RN, matches astype(bfloat16))
__device__ __forceinline__ unsigned pack_bf2(float a, float b) {
    __nv_bfloat162 p = __floats2bfloat162_rn(a, b);
    return *reinterpret_cast<unsigned*>(&p);
}

__global__ __launch_bounds__(NT, 2) void hchead_kernel(
    const float* __restrict__ x,
    const float* __restrict__ fn,
    const float* __restrict__ scale,
    const float* __restrict__ base,
    float* __restrict__ out)
{
    extern __shared__ __align__(16) unsigned char smem[];
    __nv_bfloat16* xs = reinterpret_cast<__nv_bfloat16*>(smem);          // [STOK][MH]
    float* red = reinterpret_cast<float*>(smem + STOK * MH * 2);
    float* wsh = red + NWARP * 20;

    const int tid  = threadIdx.x;
    const int warp = tid >> 5, lane = tid & 31;
    const size_t tok0 = (size_t)blockIdx.x * TOK;

    const float4* x4  = reinterpret_cast<const float4*>(x);
    const float4* fn4 = reinterpret_cast<const float4*>(fn);

    // acc: t*5+0 = sum(x^2), t*5+1+m = dot with fn[m]
    float acc[20];
#pragma unroll
    for (int i = 0; i < 20; i++) acc[i] = 0.f;

    // ------- Phase 1: stream x + fn, stash tokens 0..1 to smem, accumulate -------
#pragma unroll
    for (int k = 0; k < NK; k++) {          // 8 iterations
        const int f = tid + k * NT;         // float4 index (j = 4f)
        const float4 g0 = fn4[0 * (MH / 4) + f];
        const float4 g1 = fn4[1 * (MH / 4) + f];
        const float4 g2 = fn4[2 * (MH / 4) + f];
        const float4 g3 = fn4[3 * (MH / 4) + f];
        float4 v0 = x4[(tok0 + 0) * (MH / 4) + f];
        float4 v1 = x4[(tok0 + 1) * (MH / 4) + f];
        float4 v2 = x4[(tok0 + 2) * (MH / 4) + f];
        float4 v3 = x4[(tok0 + 3) * (MH / 4) + f];
#pragma unroll
        for (int t = 0; t < TOK; t++) {
            const float4 v = (t == 0) ? v0 : (t == 1) ? v1 : (t == 2) ? v2 : v3;
            const unsigned p0 = pack_bf2(v.x, v.y);
            const unsigned p1 = pack_bf2(v.z, v.w);
            if (t < STOK) {                  // stash rounded bf16 for phase-2
                uint2 st; st.x = p0; st.y = p1;
                reinterpret_cast<uint2*>(xs + t * MH)[f] = st;
            }
            const float x0 = bflo(p0), x1 = bfhi(p0);
            const float x2 = bflo(p1), x3 = bfhi(p1);
            acc[t * 5 + 0] += x0 * x0 + x1 * x1 + x2 * x2 + x3 * x3;
            acc[t * 5 + 1] += x0 * g0.x + x1 * g0.y + x2 * g0.z + x3 * g0.w;
            acc[t * 5 + 2] += x0 * g1.x + x1 * g1.y + x2 * g1.z + x3 * g1.w;
            acc[t * 5 + 3] += x0 * g2.x + x1 * g2.y + x2 * g2.z + x3 * g2.w;
            acc[t * 5 + 4] += x0 * g3.x + x1 * g3.y + x2 * g3.z + x3 * g3.w;
        }
    }

    // ------- Block reduction of 20 partials -------
#pragma unroll
    for (int i = 0; i < 20; i++) {
#pragma unroll
        for (int o = 16; o > 0; o >>= 1)
            acc[i] += __shfl_xor_sync(0xffffffffu, acc[i], o);
    }
    if (lane == 0) {
#pragma unroll
        for (int i = 0; i < 20; i++) red[warp * 20 + i] = acc[i];
    }
    __syncthreads();

    if (tid < TOK) {
        const int t = tid;
        float ss = 0.f, d0 = 0.f, d1 = 0.f, d2 = 0.f, d3 = 0.f;
#pragma unroll
        for (int w = 0; w < NWARP; w++) {
            ss += red[w * 20 + t * 5 + 0];
            d0 += red[w * 20 + t * 5 + 1];
            d1 += red[w * 20 + t * 5 + 2];
            d2 += red[w * 20 + t * 5 + 3];
            d3 += red[w * 20 + t * 5 + 4];
        }
        const float inv = 1.0f / sqrtf(ss * (1.0f / MH) + 1e-6f);
        const float s = scale[0];
        const float a0 = s * (d0 * inv) + base[0];
        const float a1 = s * (d1 * inv) + base[1];
        const float a2 = s * (d2 * inv) + base[2];
        const float a3 = s * (d3 * inv) + base[3];
        const float idn = 1.0f / (fabsf(a0) + fabsf(a1) + fabsf(a2) + fabsf(a3) + 1e-6f);
        wsh[t * 4 + 0] = a0 * idn;
        wsh[t * 4 + 1] = a1 * idn;
        wsh[t * 4 + 2] = a2 * idn;
        wsh[t * 4 + 3] = a3 * idn;
    }
    __syncthreads();

    // ------- Phase 2a: tokens 0..1 from smem -------
#pragma unroll
    for (int t = 0; t < STOK; t++) {
        const float w0 = wsh[t * 4 + 0], w1 = wsh[t * 4 + 1];
        const float w2 = wsh[t * 4 + 2], w3 = wsh[t * 4 + 3];
        const int h0 = tid * 8;             // 8 h per thread
        const __nv_bfloat16* bp = xs + t * MH;
        uint4 s0 = *reinterpret_cast<const uint4*>(bp + 0 * HID + h0);
        uint4 s1 = *reinterpret_cast<const uint4*>(bp + 1 * HID + h0);
        uint4 s2 = *reinterpret_cast<const uint4*>(bp + 2 * HID + h0);
        uint4 s3 = *reinterpret_cast<const uint4*>(bp + 3 * HID + h0);

        float r[8];
        r[0] = w0 * bflo(s0.x) + w1 * bflo(s1.x) + w2 * bflo(s2.x) + w3 * bflo(s3.x);
        r[1] = w0 * bfhi(s0.x) + w1 * bfhi(s1.x) + w2 * bfhi(s2.x) + w3 * bfhi(s3.x);
        r[2] = w0 * bflo(s0.y) + w1 * bflo(s1.y) + w2 * bflo(s2.y) + w3 * bflo(s3.y);
        r[3] = w0 * bfhi(s0.y) + w1 * bfhi(s1.y) + w2 * bfhi(s2.y) + w3 * bfhi(s3.y);
        r[4] = w0 * bflo(s0.z) + w1 * bflo(s1.z) + w2 * bflo(s2.z) + w3 * bflo(s3.z);
        r[5] = w0 * bfhi(s0.z) + w1 * bfhi(s1.z) + w2 * bfhi(s2.z) + w3 * bfhi(s3.z);
        r[6] = w0 * bflo(s0.w) + w1 * bflo(s1.w) + w2 * bflo(s2.w) + w3 * bflo(s3.w);
        r[7] = w0 * bfhi(s0.w) + w1 * bfhi(s1.w) + w2 * bfhi(s2.w) + w3 * bfhi(s3.w);

        float4* op = reinterpret_cast<float4*>(out + (tok0 + t) * HID + h0);
        __stcs(op + 0, make_float4(r[0], r[1], r[2], r[3]));
        __stcs(op + 1, make_float4(r[4], r[5], r[6], r[7]));
    }

    // ------- Phase 2b: tokens 2..3 re-read from L2, re-round, combine -------
#pragma unroll
    for (int t = STOK; t < TOK; t++) {
        const float w0 = wsh[t * 4 + 0], w1 = wsh[t * 4 + 1];
        const float w2 = wsh[t * 4 + 2], w3 = wsh[t * 4 + 3];
        const float4* xp = x4 + (tok0 + t) * (MH / 4);
        const int h4 = tid * 2;             // float4 index into hidden dim
        float4 a0 = xp[0 * (HID / 4) + h4 + 0];
        float4 a1 = xp[0 * (HID / 4) + h4 + 1];
        float4 b0 = xp[1 * (HID / 4) + h4 + 0];
        float4 b1 = xp[1 * (HID / 4) + h4 + 1];
        float4 c0 = xp[2 * (HID / 4) + h4 + 0];
        float4 c1 = xp[2 * (HID / 4) + h4 + 1];
        float4 d0 = xp[3 * (HID / 4) + h4 + 0];
        float4 d1 = xp[3 * (HID / 4) + h4 + 1];

        float r[8];
        {
            unsigned q0 = pack_bf2(a0.x, a0.y), q1 = pack_bf2(a0.z, a0.w);
            unsigned q2 = pack_bf2(a1.x, a1.y), q3 = pack_bf2(a1.z, a1.w);
            r[0] = w0 * bflo(q0); r[1] = w0 * bfhi(q0);
            r[2] = w0 * bflo(q1); r[3] = w0 * bfhi(q1);
            r[4] = w0 * bflo(q2); r[5] = w0 * bfhi(q2);
            r[6] = w0 * bflo(q3); r[7] = w0 * bfhi(q3);
        }
        {
            unsigned q0 = pack_bf2(b0.x, b0.y), q1 = pack_bf2(b0.z, b0.w);
            unsigned q2 = pack_bf2(b1.x, b1.y), q3 = pack_bf2(b1.z, b1.w);
            r[0] += w1 * bflo(q0); r[1] += w1 * bfhi(q0);
            r[2] += w1 * bflo(q1); r[3] += w1 * bfhi(q1);
            r[4] += w1 * bflo(q2); r[5] += w1 * bfhi(q2);
            r[6] += w1 * bflo(q3); r[7] += w1 * bfhi(q3);
        }
        {
            unsigned q0 = pack_bf2(c0.x, c0.y), q1 = pack_bf2(c0.z, c0.w);
            unsigned q2 = pack_bf2(c1.x, c1.y), q3 = pack_bf2(c1.z, c1.w);
            r[0] += w2 * bflo(q0); r[1] += w2 * bfhi(q0);
            r[2] += w2 * bflo(q1); r[3] += w2 * bfhi(q1);
            r[4] += w2 * bflo(q2); r[5] += w2 * bfhi(q2);
            r[6] += w2 * bflo(q3); r[7] += w2 * bfhi(q3);
        }
        {
            unsigned q0 = pack_bf2(d0.x, d0.y), q1 = pack_bf2(d0.z, d0.w);
            unsigned q2 = pack_bf2(d1.x, d1.y), q3 = pack_bf2(d1.z, d1.w);
            r[0] += w3 * bflo(q0); r[1] += w3 * bfhi(q0);
            r[2] += w3 * bflo(q1); r[3] += w3 * bfhi(q1);
            r[4] += w3 * bflo(q2); r[5] += w3 * bfhi(q2);
            r[6] += w3 * bflo(q3); r[7] += w3 * bfhi(q3);
        }

        float4* op = reinterpret_cast<float4*>(out + (tok0 + t) * HID) + h4;
        __stcs(op + 0, make_float4(r[0], r[1], r[2], r[3]));
        __stcs(op + 1, make_float4(r[4], r[5], r[6], r[7]));
    }
}

extern "C" void kernel_launch(void* const* d_in, const int* in_sizes, int n_in,
                              void* d_out, int out_size) {
    const float* x     = (const float*)d_in[0];   // [T, 4*4096] fp32
    const float* fn    = (const float*)d_in[1];   // [4, 16384]  fp32
    const float* scale = (const float*)d_in[2];   // [1]
    const float* base  = (const float*)d_in[3];   // [4]
    float* out = (float*)d_out;                   // [T, 4096] fp32

    const int T = in_sizes[0] / MH;               // 8192

    cudaFuncSetAttribute(hchead_kernel,
                         cudaFuncAttributeMaxDynamicSharedMemorySize, SMEM_BYTES);
    hchead_kernel<<<T / TOK, NT, SMEM_BYTES>>>(x, fn, scale, base, out);
}

// round 9
// speedup vs baseline: 1.2465x; 1.0620x over previous
#include <cuda_runtime.h>
#include <cuda_bf16.h>

#define HID 4096
#define MH 16384             // 4 * HIDDEN
#define TOK 4
#define NT 512
#define NWARP (NT / 32)      // 16
#define NK (MH / 4 / NT)     // 8 float4-iterations per token

__device__ __forceinline__ float bflo(unsigned u) {   // low bf16 -> f32
    return __uint_as_float(u << 16);
}
__device__ __forceinline__ float bfhi(unsigned u) {   // high bf16 -> f32
    return __uint_as_float(u & 0xFFFF0000u);
}
// round fp32 pair -> packed bf16x2 (RN, matches astype(bfloat16))
__device__ __forceinline__ unsigned pack_bf2(float a, float b) {
    __nv_bfloat162 p = __floats2bfloat162_rn(a, b);
    return *reinterpret_cast<unsigned*>(&p);
}

__global__ __launch_bounds__(NT, 2) void hchead_kernel(
    const float* __restrict__ x,
    const float* __restrict__ fn,
    const float* __restrict__ scale,
    const float* __restrict__ base,
    float* __restrict__ out)
{
    __shared__ float red[NWARP * 20];
    __shared__ float wsh[TOK * 4];

    const int tid  = threadIdx.x;
    const int warp = tid >> 5, lane = tid & 31;
    const size_t tok0 = (size_t)blockIdx.x * TOK;

    const float4* x4  = reinterpret_cast<const float4*>(x);
    const float4* fn4 = reinterpret_cast<const float4*>(fn);

    // acc: t*5+0 = sum(x^2), t*5+1+m = dot with fn[m]
    float acc[20];
#pragma unroll
    for (int i = 0; i < 20; i++) acc[i] = 0.f;

    // ------- Phase 1: stream x (DRAM) + fn (L2), accumulate sums -------
#pragma unroll
    for (int k = 0; k < NK; k++) {          // 8 iterations
        const int f = tid + k * NT;         // float4 index (j = 4f)
        const float4 g0 = fn4[0 * (MH / 4) + f];
        const float4 g1 = fn4[1 * (MH / 4) + f];
        const float4 g2 = fn4[2 * (MH / 4) + f];
        const float4 g3 = fn4[3 * (MH / 4) + f];
        float4 v0 = x4[(tok0 + 0) * (MH / 4) + f];
        float4 v1 = x4[(tok0 + 1) * (MH / 4) + f];
        float4 v2 = x4[(tok0 + 2) * (MH / 4) + f];
        float4 v3 = x4[(tok0 + 3) * (MH / 4) + f];
#pragma unroll
        for (int t = 0; t < TOK; t++) {
            const float4 v = (t == 0) ? v0 : (t == 1) ? v1 : (t == 2) ? v2 : v3;
            const unsigned p0 = pack_bf2(v.x, v.y);
            const unsigned p1 = pack_bf2(v.z, v.w);
            const float x0 = bflo(p0), x1 = bfhi(p0);
            const float x2 = bflo(p1), x3 = bfhi(p1);
            acc[t * 5 + 0] += x0 * x0 + x1 * x1 + x2 * x2 + x3 * x3;
            acc[t * 5 + 1] += x0 * g0.x + x1 * g0.y + x2 * g0.z + x3 * g0.w;
            acc[t * 5 + 2] += x0 * g1.x + x1 * g1.y + x2 * g1.z + x3 * g1.w;
            acc[t * 5 + 3] += x0 * g2.x + x1 * g2.y + x2 * g2.z + x3 * g2.w;
            acc[t * 5 + 4] += x0 * g3.x + x1 * g3.y + x2 * g3.z + x3 * g3.w;
        }
    }

    // ------- Block reduction of 20 partials -------
#pragma unroll
    for (int i = 0; i < 20; i++) {
#pragma unroll
        for (int o = 16; o > 0; o >>= 1)
            acc[i] += __shfl_xor_sync(0xffffffffu, acc[i], o);
    }
    if (lane == 0) {
#pragma unroll
        for (int i = 0; i < 20; i++) red[warp * 20 + i] = acc[i];
    }
    __syncthreads();

    if (tid < TOK) {
        const int t = tid;
        float ss = 0.f, d0 = 0.f, d1 = 0.f, d2 = 0.f, d3 = 0.f;
#pragma unroll
        for (int w = 0; w < NWARP; w++) {
            ss += red[w * 20 + t * 5 + 0];
            d0 += red[w * 20 + t * 5 + 1];
            d1 += red[w * 20 + t * 5 + 2];
            d2 += red[w * 20 + t * 5 + 3];
            d3 += red[w * 20 + t * 5 + 4];
        }
        const float inv = 1.0f / sqrtf(ss * (1.0f / MH) + 1e-6f);
        const float s = scale[0];
        const float a0 = s * (d0 * inv) + base[0];
        const float a1 = s * (d1 * inv) + base[1];
        const float a2 = s * (d2 * inv) + base[2];
        const float a3 = s * (d3 * inv) + base[3];
        const float idn = 1.0f / (fabsf(a0) + fabsf(a1) + fabsf(a2) + fabsf(a3) + 1e-6f);
        wsh[t * 4 + 0] = a0 * idn;
        wsh[t * 4 + 1] = a1 * idn;
        wsh[t * 4 + 2] = a2 * idn;
        wsh[t * 4 + 3] = a3 * idn;
    }
    __syncthreads();

    // ------- Phase 2: re-read x (evict-first), re-round, combine, store -------
    // Each thread: 8 h-positions per token (2 float4 outputs).
#pragma unroll
    for (int t = 0; t < TOK; t++) {
        const float w0 = wsh[t * 4 + 0], w1 = wsh[t * 4 + 1];
        const float w2 = wsh[t * 4 + 2], w3 = wsh[t * 4 + 3];
        const float4* xp = x4 + (tok0 + t) * (MH / 4);
        const int h4 = tid * 2;             // float4 index into hidden dim
        // 8 independent loads, evict-first (each line dead after this use)
        float4 a0 = __ldcs(xp + 0 * (HID / 4) + h4 + 0);
        float4 a1 = __ldcs(xp + 0 * (HID / 4) + h4 + 1);
        float4 b0 = __ldcs(xp + 1 * (HID / 4) + h4 + 0);
        float4 b1 = __ldcs(xp + 1 * (HID / 4) + h4 + 1);
        float4 c0 = __ldcs(xp + 2 * (HID / 4) + h4 + 0);
        float4 c1 = __ldcs(xp + 2 * (HID / 4) + h4 + 1);
        float4 d0 = __ldcs(xp + 3 * (HID / 4) + h4 + 0);
        float4 d1 = __ldcs(xp + 3 * (HID / 4) + h4 + 1);

        float r[8];
        {
            unsigned q0 = pack_bf2(a0.x, a0.y), q1 = pack_bf2(a0.z, a0.w);
            unsigned q2 = pack_bf2(a1.x, a1.y), q3 = pack_bf2(a1.z, a1.w);
            r[0] = w0 * bflo(q0); r[1] = w0 * bfhi(q0);
            r[2] = w0 * bflo(q1); r[3] = w0 * bfhi(q1);
            r[4] = w0 * bflo(q2); r[5] = w0 * bfhi(q2);
            r[6] = w0 * bflo(q3); r[7] = w0 * bfhi(q3);
        }
        {
            unsigned q0 = pack_bf2(b0.x, b0.y), q1 = pack_bf2(b0.z, b0.w);
            unsigned q2 = pack_bf2(b1.x, b1.y), q3 = pack_bf2(b1.z, b1.w);
            r[0] += w1 * bflo(q0); r[1] += w1 * bfhi(q0);
            r[2] += w1 * bflo(q1); r[3] += w1 * bfhi(q1);
            r[4] += w1 * bflo(q2); r[5] += w1 * bfhi(q2);
            r[6] += w1 * bflo(q3); r[7] += w1 * bfhi(q3);
        }
        {
            unsigned q0 = pack_bf2(c0.x, c0.y), q1 = pack_bf2(c0.z, c0.w);
            unsigned q2 = pack_bf2(c1.x, c1.y), q3 = pack_bf2(c1.z, c1.w);
            r[0] += w2 * bflo(q0); r[1] += w2 * bfhi(q0);
            r[2] += w2 * bflo(q1); r[3] += w2 * bfhi(q1);
            r[4] += w2 * bflo(q2); r[5] += w2 * bfhi(q2);
            r[6] += w2 * bflo(q3); r[7] += w2 * bfhi(q3);
        }
        {
            unsigned q0 = pack_bf2(d0.x, d0.y), q1 = pack_bf2(d0.z, d0.w);
            unsigned q2 = pack_bf2(d1.x, d1.y), q3 = pack_bf2(d1.z, d1.w);
            r[0] += w3 * bflo(q0); r[1] += w3 * bfhi(q0);
            r[2] += w3 * bflo(q1); r[3] += w3 * bfhi(q1);
            r[4] += w3 * bflo(q2); r[5] += w3 * bfhi(q2);
            r[6] += w3 * bflo(q3); r[7] += w3 * bfhi(q3);
        }

        float4* op = reinterpret_cast<float4*>(out + (tok0 + t) * HID) + h4;
        __stcs(op + 0, make_float4(r[0], r[1], r[2], r[3]));
        __stcs(op + 1, make_float4(r[4], r[5], r[6], r[7]));
    }
}

extern "C" void kernel_launch(void* const* d_in, const int* in_sizes, int n_in,
                              void* d_out, int out_size) {
    const float* x     = (const float*)d_in[0];   // [T, 4*4096] fp32
    const float* fn    = (const float*)d_in[1];   // [4, 16384]  fp32
    const float* scale = (const float*)d_in[2];   // [1]
    const float* base  = (const float*)d_in[3];   // [4]
    float* out = (float*)d_out;                   // [T, 4096] fp32

    const int T = in_sizes[0] / MH;               // 8192
    hchead_kernel<<<T / TOK, NT>>>(x, fn, scale, base, out);
}